// round 3
// baseline (speedup 1.0000x reference)
#include <cuda_runtime.h>
#include <cstdint>

// jax threefry mode: 1 = threefry_partitionable (jax >= 0.5.0 default), 0 = legacy
#ifndef RNG_PARTITIONABLE
#define RNG_PARTITIONABLE 1
#endif

#define NROWS  65536
#define HROWS  32768
#define NC     1000
#define DD     64
#define H_COORD 32768000u   // half of 32*2048*1000
#define H_CODE  1048576u    // half of 32*2048*32
#define QOFF   0
#define QCOFF  4194304      // 65536*64

__device__ double g_parts[8192];   // [0,4096): coord blocks, [4096,8192): code blocks

// ---------------- threefry2x32 (matches jax) ----------------
__host__ __device__ __forceinline__ uint32_t rotl32(uint32_t x, int r) {
#ifdef __CUDA_ARCH__
    return __funnelshift_l(x, x, r);
#else
    return (x << r) | (x >> (32 - r));
#endif
}

struct U2 { uint32_t x, y; };

__host__ __device__ __forceinline__ U2 tf2x32(uint32_t k0, uint32_t k1,
                                              uint32_t x0, uint32_t x1) {
    uint32_t k2 = k0 ^ k1 ^ 0x1BD11BDAu;
    x0 += k0; x1 += k1;
#define TFR(r) { x0 += x1; x1 = rotl32(x1, r); x1 ^= x0; }
    TFR(13) TFR(15) TFR(26) TFR(6)
    x0 += k1; x1 += k2 + 1u;
    TFR(17) TFR(29) TFR(16) TFR(24)
    x0 += k2; x1 += k0 + 2u;
    TFR(13) TFR(15) TFR(26) TFR(6)
    x0 += k0; x1 += k1 + 3u;
    TFR(17) TFR(29) TFR(16) TFR(24)
    x0 += k1; x1 += k2 + 4u;
    TFR(13) TFR(15) TFR(26) TFR(6)
    x0 += k2; x1 += k0 + 5u;
#undef TFR
    U2 r; r.x = x0; r.y = x1; return r;
}

// gumbel = -log(1e-20 - log(u + 1e-20)), u = bitcast(bits>>9 | 0x3f800000) - 1
// Near u==1 MUFU's absolute error wrecks relative accuracy of ln(u); use a
// log1p series for d = 1-u <= 1/16 (exact d by Sterbenz since u >= 0.5 there).
__device__ __forceinline__ float bits_to_gumbel(uint32_t bits) {
    float u = __uint_as_float((bits >> 9) | 0x3f800000u) - 1.0f;
    float d = 1.0f - u;
    float poly = -d * fmaf(d, fmaf(d, fmaf(d, 0.25f, 0.33333334f), 0.5f), 1.0f);
    float lf = __logf(u + 1e-20f);
    float lnu = (d <= 0.0625f) ? poly : lf;   // lnu = log(u + eps) <= 0
    float t = 1e-20f - lnu;                   // > 0
    return -__logf(t);
}

// ---------------- warp helpers ----------------
__device__ __forceinline__ float warp_sum(float v) {
    #pragma unroll
    for (int o = 16; o; o >>= 1) v += __shfl_xor_sync(0xffffffffu, v, o);
    return v;
}
__device__ __forceinline__ float grp8_max(float v) {
    v = fmaxf(v, __shfl_xor_sync(0xffffffffu, v, 4));
    v = fmaxf(v, __shfl_xor_sync(0xffffffffu, v, 2));
    v = fmaxf(v, __shfl_xor_sync(0xffffffffu, v, 1));
    return v;
}
__device__ __forceinline__ float grp8_sum(float v) {
    v += __shfl_xor_sync(0xffffffffu, v, 4);
    v += __shfl_xor_sync(0xffffffffu, v, 2);
    v += __shfl_xor_sync(0xffffffffu, v, 1);
    return v;
}

// pairwise-rescaled reduce of (max m, S, T) across the warp
__device__ __forceinline__ void combineST(float& m, float& S, float& T) {
    #pragma unroll
    for (int o = 16; o; o >>= 1) {
        float mo = __shfl_xor_sync(0xffffffffu, m, o);
        float So = __shfl_xor_sync(0xffffffffu, S, o);
        float To = __shfl_xor_sync(0xffffffffu, T, o);
        float mn = fmaxf(m, mo);
        float c1 = __expf(m - mn), c2 = __expf(mo - mn);
        S = fmaf(S, c1, So * c2);
        T = fmaf(T, c1, To * c2);
        m = mn;
    }
}
__device__ __forceinline__ void combineSG(float& m, float& S, float& gx, float& gy, float& gz) {
    #pragma unroll
    for (int o = 16; o; o >>= 1) {
        float mo  = __shfl_xor_sync(0xffffffffu, m, o);
        float So  = __shfl_xor_sync(0xffffffffu, S, o);
        float gxo = __shfl_xor_sync(0xffffffffu, gx, o);
        float gyo = __shfl_xor_sync(0xffffffffu, gy, o);
        float gzo = __shfl_xor_sync(0xffffffffu, gz, o);
        float mn = fmaxf(m, mo);
        float c1 = __expf(m - mn), c2 = __expf(mo - mn);
        S  = fmaf(S,  c1, So  * c2);
        gx = fmaf(gx, c1, gxo * c2);
        gy = fmaf(gy, c1, gyo * c2);
        gz = fmaf(gz, c1, gzo * c2);
        m = mn;
    }
}

// =======================================================================
// Coordinate path: one warp handles row pair (r, r+HROWS); single fused
// streaming pass with online softmax states; logits collapsed to 3-FMA.
// =======================================================================
__global__ void __launch_bounds__(256, 3)
k_coord(const float* __restrict__ inputs, const float* __restrict__ linear_w,
        const float* __restrict__ linear_b, float* __restrict__ out,
        uint32_t kc0, uint32_t kc1)
{
    __shared__ float4 grid_s[NC];
    __shared__ float  Ws[DD * 3];
    __shared__ float  bs[DD];
    __shared__ double kl_s[8];

    const int tid = threadIdx.x;
    for (int i = tid; i < DD * 3; i += 256) Ws[i] = linear_w[i];
    for (int i = tid; i < DD;     i += 256) bs[i] = linear_b[i];
    for (int n = tid; n < NC; n += 256) {
        int i10 = n / 100;
        int j10 = (n / 10) % 10;
        int k10 = n % 10;
        // meshgrid 'xy': g[n] = (x[j], x[i], x[k]), x[t] = t * (1.5/9) (fp64 -> fp32)
        grid_s[n] = make_float4((float)(j10 * (1.5 / 9.0)),
                                (float)(i10 * (1.5 / 9.0)),
                                (float)(k10 * (1.5 / 9.0)), 0.0f);
    }
    __syncthreads();

    const int w = tid >> 5, lane = tid & 31;
    const int rlo = blockIdx.x * 8 + w;
    const int rhi = rlo + HROWS;

    // per-row 3-proj + bias-dot (distributed over lanes, warp-reduced)
    float il0 = inputs[(size_t)rlo * DD + lane];
    float il1 = inputs[(size_t)rlo * DD + 32 + lane];
    float ih0 = inputs[(size_t)rhi * DD + lane];
    float ih1 = inputs[(size_t)rhi * DD + 32 + lane];
    float w00 = Ws[lane * 3 + 0], w01 = Ws[lane * 3 + 1], w02 = Ws[lane * 3 + 2];
    float w10 = Ws[(lane + 32) * 3 + 0], w11 = Ws[(lane + 32) * 3 + 1], w12 = Ws[(lane + 32) * 3 + 2];
    float b0 = bs[lane], b1 = bs[lane + 32];

    float p0l = warp_sum(fmaf(il0, w00, il1 * w10));
    float p1l = warp_sum(fmaf(il0, w01, il1 * w11));
    float p2l = warp_sum(fmaf(il0, w02, il1 * w12));
    float ccl = warp_sum(fmaf(il0, b0,  il1 * b1));
    float p0h = warp_sum(fmaf(ih0, w00, ih1 * w10));
    float p1h = warp_sum(fmaf(ih0, w01, ih1 * w11));
    float p2h = warp_sum(fmaf(ih0, w02, ih1 * w12));
    float cch = warp_sum(fmaf(ih0, b0,  ih1 * b1));

    float m1l = -1e30f, Sl = 0.f, Tl = 0.f;
    float m1h = -1e30f, Sh = 0.f, Th = 0.f;
    float m2l = -1e30f, S2l = 0.f, gxl = 0.f, gyl = 0.f, gzl = 0.f;
    float m2h = -1e30f, S2h = 0.f, gxh = 0.f, gyh = 0.f, gzh = 0.f;

    uint32_t idx = (uint32_t)rlo * 1000u + (uint32_t)lane;

    for (int n = lane; n < NC; n += 32, idx += 32) {
        float4 g = grid_s[n];
        float xl = fmaf(p0l, g.x, fmaf(p1l, g.y, fmaf(p2l, g.z, ccl)));
        float xh = fmaf(p0h, g.x, fmaf(p1h, g.y, fmaf(p2h, g.z, cch)));

        // online logsumexp + E[x] state (for logZ and KL)
        if (xl > m1l) { float c = __expf(m1l - xl); Sl *= c; Tl *= c; m1l = xl; }
        float e1l = __expf(xl - m1l); Sl += e1l; Tl = fmaf(e1l, xl, Tl);
        if (xh > m1h) { float c = __expf(m1h - xh); Sh *= c; Th *= c; m1h = xh; }
        float e1h = __expf(xh - m1h); Sh += e1h; Th = fmaf(e1h, xh, Th);

        // gumbel noise (threefry)
        float gl, gh;
#if RNG_PARTITIONABLE
        U2 A = tf2x32(kc0, kc1, 0u, idx);
        U2 B = tf2x32(kc0, kc1, 0u, idx + H_COORD);
        gl = bits_to_gumbel(A.x ^ A.y);
        gh = bits_to_gumbel(B.x ^ B.y);
#else
        U2 A = tf2x32(kc0, kc1, idx, idx + H_COORD);
        gl = bits_to_gumbel(A.x);
        gh = bits_to_gumbel(A.y);
#endif
        // gumbel-softmax weighted grid sum; softmax((logp+g)/2) == softmax((x+g)/2)
        float zl = (xl + gl) * 0.5f;
        if (zl > m2l) { float c = __expf(m2l - zl); S2l *= c; gxl *= c; gyl *= c; gzl *= c; m2l = zl; }
        float e2l = __expf(zl - m2l);
        S2l += e2l; gxl = fmaf(e2l, g.x, gxl); gyl = fmaf(e2l, g.y, gyl); gzl = fmaf(e2l, g.z, gzl);

        float zh = (xh + gh) * 0.5f;
        if (zh > m2h) { float c = __expf(m2h - zh); S2h *= c; gxh *= c; gyh *= c; gzh *= c; m2h = zh; }
        float e2h = __expf(zh - m2h);
        S2h += e2h; gxh = fmaf(e2h, g.x, gxh); gyh = fmaf(e2h, g.y, gyh); gzh = fmaf(e2h, g.z, gzh);
    }

    combineST(m1l, Sl, Tl);
    combineST(m1h, Sh, Th);
    combineSG(m2l, S2l, gxl, gyl, gzl);
    combineSG(m2h, S2h, gxh, gyh, gzh);

    float lzl = m1l + __logf(Sl);
    float lzh = m1h + __logf(Sh);
    float kll = Tl / Sl - lzl + 6.907755278982137f;   // + log(1000)
    float klh = Th / Sh - lzh + 6.907755278982137f;

    float invl = 1.0f / S2l, invh = 1.0f / S2h;
    gxl *= invl; gyl *= invl; gzl *= invl;
    gxh *= invh; gyh *= invh; gzh *= invh;

    // quantized_coord[r,d] = W[d,:] . sg + b[d]
    out[QCOFF + (size_t)rlo * 64 + lane]      = fmaf(w00, gxl, fmaf(w01, gyl, fmaf(w02, gzl, b0)));
    out[QCOFF + (size_t)rlo * 64 + 32 + lane] = fmaf(w10, gxl, fmaf(w11, gyl, fmaf(w12, gzl, b1)));
    out[QCOFF + (size_t)rhi * 64 + lane]      = fmaf(w00, gxh, fmaf(w01, gyh, fmaf(w02, gzh, b0)));
    out[QCOFF + (size_t)rhi * 64 + 32 + lane] = fmaf(w10, gxh, fmaf(w11, gyh, fmaf(w12, gzh, b1)));

    if (lane == 0) kl_s[w] = (double)kll + (double)klh;
    __syncthreads();
    if (tid == 0) {
        double s = 0;
        #pragma unroll
        for (int i = 0; i < 8; i++) s += kl_s[i];
        g_parts[blockIdx.x] = s;
    }
}

// =======================================================================
// Per-codebook path: one warp per row pair. K=4 codebooks x N=8 codes,
// lane = k*8+n. All operands staged in smem (transposed / padded for
// conflict-free access).
// =======================================================================
__global__ void __launch_bounds__(256)
k_code(const float* __restrict__ inputs, const float* __restrict__ emb,
       const float* __restrict__ lin_ws, float* __restrict__ out,
       uint32_t kp0, uint32_t kp1)
{
    __shared__ float  lwt[64 * 64];      // [d][ke] transposed lin_ws
    __shared__ float  emb_s[32 * 17];    // padded rows
    __shared__ float  in_s[8][2][64];
    __shared__ float  h_s[8][2][64];
    __shared__ float  ip_s[8][2][32];
    __shared__ double kl_s[8];

    const int tid = threadIdx.x;
    for (int i = tid; i < 4096; i += 256) {
        int ke = i >> 6, d = i & 63;
        lwt[d * 64 + ke] = lin_ws[i];    // lin_ws[(k*16+e)*64 + d]
    }
    for (int i = tid; i < 512; i += 256)
        emb_s[(i >> 4) * 17 + (i & 15)] = emb[i];
    __syncthreads();

    const int w = tid >> 5, lane = tid & 31;
    const int rlo = blockIdx.x * 8 + w;
    const int rhi = rlo + HROWS;

    in_s[w][0][lane]      = inputs[(size_t)rlo * 64 + lane];
    in_s[w][0][lane + 32] = inputs[(size_t)rlo * 64 + lane + 32];
    in_s[w][1][lane]      = inputs[(size_t)rhi * 64 + lane];
    in_s[w][1][lane + 32] = inputs[(size_t)rhi * 64 + lane + 32];
    __syncwarp();

    // h[k,e] = inputs . lin_ws[k,e,:]  (each lane computes 2 h values per row)
    float hl0 = 0.f, hl1 = 0.f, hh0 = 0.f, hh1 = 0.f;
    const float2* lwt2 = reinterpret_cast<const float2*>(lwt);
    #pragma unroll 8
    for (int d = 0; d < 64; d++) {
        float2 wv = lwt2[d * 32 + lane];
        float xl = in_s[w][0][d], xh = in_s[w][1][d];
        hl0 = fmaf(xl, wv.x, hl0); hl1 = fmaf(xl, wv.y, hl1);
        hh0 = fmaf(xh, wv.x, hh0); hh1 = fmaf(xh, wv.y, hh1);
    }
    h_s[w][0][2 * lane] = hl0; h_s[w][0][2 * lane + 1] = hl1;
    h_s[w][1][2 * lane] = hh0; h_s[w][1][2 * lane + 1] = hh1;
    __syncwarp();

    // xp[k,n] = h[k,:] . emb[k*8+n,:]   (lane -> (k = lane>>3, n = lane&7))
    const int kk = lane >> 3;
    float xpl = 0.f, xph = 0.f;
    #pragma unroll
    for (int e = 0; e < 16; e++) {
        float ev = emb_s[lane * 17 + e];
        xpl = fmaf(h_s[w][0][kk * 16 + e], ev, xpl);
        xph = fmaf(h_s[w][1][kk * 16 + e], ev, xph);
    }

    // log_softmax over the 8-lane group + KL vs uniform(1/8)
    float ml = grp8_max(xpl), mh = grp8_max(xph);
    float el = __expf(xpl - ml), eh = __expf(xph - mh);
    float sl = grp8_sum(el), sh2 = grp8_sum(eh);
    float lzl = ml + __logf(sl), lzh = mh + __logf(sh2);
    float lpl = xpl - lzl, lph = xph - lzh;
    float kl_l = grp8_sum(el * (lpl + 2.0794415416798357f)) / sl;
    float kl_h = grp8_sum(eh * (lph + 2.0794415416798357f)) / sh2;

    // gumbel
    uint32_t idx = (uint32_t)rlo * 32u + (uint32_t)lane;
    float gl, gh;
#if RNG_PARTITIONABLE
    U2 A = tf2x32(kp0, kp1, 0u, idx);
    U2 B = tf2x32(kp0, kp1, 0u, idx + H_CODE);
    gl = bits_to_gumbel(A.x ^ A.y);
    gh = bits_to_gumbel(B.x ^ B.y);
#else
    U2 A = tf2x32(kp0, kp1, idx, idx + H_CODE);
    gl = bits_to_gumbel(A.x);
    gh = bits_to_gumbel(A.y);
#endif

    float zl = (lpl + gl) * 0.5f, zh = (lph + gh) * 0.5f;
    float m2l = grp8_max(zl), m2h = grp8_max(zh);
    float e2l = __expf(zl - m2l), e2h = __expf(zh - m2h);
    float s2l = grp8_sum(e2l), s2h = grp8_sum(e2h);
    ip_s[w][0][lane] = e2l / s2l;
    ip_s[w][1][lane] = e2h / s2h;
    __syncwarp();

    // quantized[r, k*16+e] = sum_n ip[k,n] * emb[k*8+n, e]   (2 outputs/lane)
    const int k2 = lane >> 3;
    const int e0 = (2 * lane) & 15;
    float ql0 = 0.f, ql1 = 0.f, qh0 = 0.f, qh1 = 0.f;
    #pragma unroll
    for (int nn = 0; nn < 8; nn++) {
        float ipl = ip_s[w][0][k2 * 8 + nn];
        float iph = ip_s[w][1][k2 * 8 + nn];
        float ev0 = emb_s[(k2 * 8 + nn) * 17 + e0];
        float ev1 = emb_s[(k2 * 8 + nn) * 17 + e0 + 1];
        ql0 = fmaf(ipl, ev0, ql0); ql1 = fmaf(ipl, ev1, ql1);
        qh0 = fmaf(iph, ev0, qh0); qh1 = fmaf(iph, ev1, qh1);
    }
    float2* o2 = reinterpret_cast<float2*>(out);
    o2[((size_t)rlo * 64 + 2 * lane) / 2] = make_float2(ql0, ql1);
    o2[((size_t)rhi * 64 + 2 * lane) / 2] = make_float2(qh0, qh1);

    // KL: group-uniform values; pick one lane per group, sum across warp
    float klrow = ((lane & 7) == 0) ? (kl_l + kl_h) : 0.0f;
    klrow = warp_sum(klrow);
    if (lane == 0) kl_s[w] = (double)klrow;
    __syncthreads();
    if (tid == 0) {
        double s = 0;
        #pragma unroll
        for (int i = 0; i < 8; i++) s += kl_s[i];
        g_parts[4096 + blockIdx.x] = s;
    }
}

// Deterministic final reduction of the KL partials -> loss scalar
__global__ void k_final(float* __restrict__ out, int loss_idx) {
    __shared__ double sh[256];
    double s = 0;
    for (int i = threadIdx.x; i < 8192; i += 256) s += g_parts[i];
    sh[threadIdx.x] = s;
    __syncthreads();
    #pragma unroll
    for (int o = 128; o; o >>= 1) {
        if (threadIdx.x < o) sh[threadIdx.x] += sh[threadIdx.x + o];
        __syncthreads();
    }
    if (threadIdx.x == 0) out[loss_idx] = (float)(sh[0] / 5.0);
}

extern "C" void kernel_launch(void* const* d_in, const int* in_sizes, int n_in,
                              void* d_out, int out_size) {
    const float* inputs   = (const float*)d_in[0];
    const float* linear_w = (const float*)d_in[1];
    const float* linear_b = (const float*)d_in[2];
    const float* emb      = (const float*)d_in[3];
    const float* lin_ws   = (const float*)d_in[4];
    float* out = (float*)d_out;

    // kc, kp = jax.random.split(jax.random.key(42))
#if RNG_PARTITIONABLE
    // partitionable (fold-like) split: counts = 64-bit iota split hi/lo:
    // key_i = cipher(k0=0, k1=42, x0=0, x1=i) -> (out.x, out.y)
    U2 a = tf2x32(0u, 42u, 0u, 0u);
    U2 b = tf2x32(0u, 42u, 0u, 1u);
    uint32_t kc0 = a.x, kc1 = a.y;
    uint32_t kp0 = b.x, kp1 = b.y;
#else
    // legacy split: threefry_2x32(key, iota(4)); lanes cipher(0,2), cipher(1,3);
    // concat(outx, outy).reshape(2,2): kc = (a.x, b.x), kp = (a.y, b.y)
    U2 a = tf2x32(0u, 42u, 0u, 2u);
    U2 b = tf2x32(0u, 42u, 1u, 3u);
    uint32_t kc0 = a.x, kc1 = b.x;
    uint32_t kp0 = a.y, kp1 = b.y;
#endif

    k_coord<<<4096, 256>>>(inputs, linear_w, linear_b, out, kc0, kc1);
    k_code <<<4096, 256>>>(inputs, emb, lin_ws, out, kp0, kp1);
    k_final<<<1, 256>>>(out, out_size - 1);
}

// round 4
// speedup vs baseline: 1.1859x; 1.1859x over previous
#include <cuda_runtime.h>
#include <cstdint>

// jax threefry mode: 1 = threefry_partitionable (jax >= 0.5.0 default), 0 = legacy
#ifndef RNG_PARTITIONABLE
#define RNG_PARTITIONABLE 1
#endif

#define HROWS  32768
#define NC     1000
#define H_COORD 32768000u   // half of 32*2048*1000
#define H_CODE  1048576u    // half of 32*2048*32
#define QCOFF  4194304      // 65536*64

__device__ double g_parts[8192];

// ---------------- threefry2x32 (matches jax) ----------------
__host__ __device__ __forceinline__ uint32_t rotl32(uint32_t x, int r) {
#ifdef __CUDA_ARCH__
    return __funnelshift_l(x, x, r);
#else
    return (x << r) | (x >> (32 - r));
#endif
}

struct U2 { uint32_t x, y; };

__host__ __device__ __forceinline__ U2 tf2x32(uint32_t k0, uint32_t k1,
                                              uint32_t x0, uint32_t x1) {
    uint32_t k2 = k0 ^ k1 ^ 0x1BD11BDAu;
    x0 += k0; x1 += k1;
#define TFR(r) { x0 += x1; x1 = rotl32(x1, r); x1 ^= x0; }
    TFR(13) TFR(15) TFR(26) TFR(6)
    x0 += k1; x1 += k2 + 1u;
    TFR(17) TFR(29) TFR(16) TFR(24)
    x0 += k2; x1 += k0 + 2u;
    TFR(13) TFR(15) TFR(26) TFR(6)
    x0 += k0; x1 += k1 + 3u;
    TFR(17) TFR(29) TFR(16) TFR(24)
    x0 += k1; x1 += k2 + 4u;
    TFR(13) TFR(15) TFR(26) TFR(6)
    x0 += k2; x1 += k0 + 5u;
#undef TFR
    U2 r; r.x = x0; r.y = x1; return r;
}

__device__ __forceinline__ float ex2a(float x) {
    float r; asm("ex2.approx.ftz.f32 %0, %1;" : "=f"(r) : "f"(x)); return r;
}
__device__ __forceinline__ float lg2a(float x) {
    float r; asm("lg2.approx.ftz.f32 %0, %1;" : "=f"(r) : "f"(x)); return r;
}

// Returns lg2(t) where t = 1e-20 - ln(u + 1e-20), u = bits-derived uniform.
// gumbel g = -ln(t) = -ln2 * lg2(t). log1p polynomial near u==1 keeps relative
// accuracy where MUFU's absolute error would blow up.
__device__ __forceinline__ float gumbel_lg2t(uint32_t bits) {
    float u = __uint_as_float((bits >> 9) | 0x3f800000u) - 1.0f;
    float d = 1.0f - u;                       // exact (Sterbenz) for u >= 0.5
    float poly = -d * fmaf(d, fmaf(d, fmaf(d, 0.25f, 0.33333334f), 0.5f), 1.0f);
    float lf = 0.6931471805599453f * lg2a(u + 1e-20f);
    float lnu = (d <= 0.0625f) ? poly : lf;   // ln(u + eps) <= 0
    return lg2a(1e-20f - lnu);
}

// natural-log gumbel (used in the tiny code path)
__device__ __forceinline__ float bits_to_gumbel(uint32_t bits) {
    return -0.6931471805599453f * gumbel_lg2t(bits);
}

__device__ __forceinline__ float warp_sum(float v) {
    #pragma unroll
    for (int o = 16; o; o >>= 1) v += __shfl_xor_sync(0xffffffffu, v, o);
    return v;
}
__device__ __forceinline__ float grp8_max(float v) {
    v = fmaxf(v, __shfl_xor_sync(0xffffffffu, v, 4));
    v = fmaxf(v, __shfl_xor_sync(0xffffffffu, v, 2));
    v = fmaxf(v, __shfl_xor_sync(0xffffffffu, v, 1));
    return v;
}
__device__ __forceinline__ float grp8_sum(float v) {
    v += __shfl_xor_sync(0xffffffffu, v, 4);
    v += __shfl_xor_sync(0xffffffffu, v, 2);
    v += __shfl_xor_sync(0xffffffffu, v, 1);
    return v;
}

// ---------------- shared-memory layouts ----------------
struct CoordSm {
    float4 grid[NC];     // 16000 B
    float  Ws[192];
    float  bs[64];
    double kl[8];
};
struct CodeSm {
    float  lwt[4096];       // [d][ke] transposed lin_ws
    float  emb_s[32 * 17];  // padded rows
    float  in_s[8][2][64];
    float  h_s[8][2][64];
    float  ip_s[8][2][32];
    double kl[8];
};
union SmU { CoordSm c; CodeSm q; };

// =======================================================================
// Coordinate path: branch-free streaming loop. Exact max known up front:
// x = p.g + c is linear on the grid box, corners are grid points, so
// M1 = c + 1.5*(relu(p0)+relu(p1)+relu(p2)). Gumbel in [-3.83, 15.95]
// => fixed shift M2 = (M1+16)/2 is safe for the second softmax.
// =======================================================================
__device__ __forceinline__ void do_coord(
    CoordSm& sm, int pairBase,
    const float* __restrict__ inputs, const float* __restrict__ linear_w,
    const float* __restrict__ linear_b, float* __restrict__ out,
    uint32_t kc0, uint32_t kc1, int bid)
{
    const int tid = threadIdx.x;
    for (int i = tid; i < 192; i += 256) sm.Ws[i] = linear_w[i];
    for (int i = tid; i < 64;  i += 256) sm.bs[i] = linear_b[i];
    for (int n = tid; n < NC; n += 256) {
        int i10 = n / 100, j10 = (n / 10) % 10, k10 = n % 10;
        // meshgrid 'xy': g[n] = (x[j], x[i], x[k])
        sm.grid[n] = make_float4((float)(j10 * (1.5 / 9.0)),
                                 (float)(i10 * (1.5 / 9.0)),
                                 (float)(k10 * (1.5 / 9.0)), 0.0f);
    }
    __syncthreads();

    const int w = tid >> 5, lane = tid & 31;
    const int rlo = pairBase + w;
    const int rhi = rlo + HROWS;

    float il0 = inputs[(size_t)rlo * 64 + lane];
    float il1 = inputs[(size_t)rlo * 64 + 32 + lane];
    float ih0 = inputs[(size_t)rhi * 64 + lane];
    float ih1 = inputs[(size_t)rhi * 64 + 32 + lane];
    float w00 = sm.Ws[lane * 3 + 0], w01 = sm.Ws[lane * 3 + 1], w02 = sm.Ws[lane * 3 + 2];
    float w10 = sm.Ws[(lane + 32) * 3 + 0], w11 = sm.Ws[(lane + 32) * 3 + 1], w12 = sm.Ws[(lane + 32) * 3 + 2];
    float b0 = sm.bs[lane], b1 = sm.bs[lane + 32];

    float p0l = warp_sum(fmaf(il0, w00, il1 * w10));
    float p1l = warp_sum(fmaf(il0, w01, il1 * w11));
    float p2l = warp_sum(fmaf(il0, w02, il1 * w12));
    float ccl = warp_sum(fmaf(il0, b0,  il1 * b1));
    float p0h = warp_sum(fmaf(ih0, w00, ih1 * w10));
    float p1h = warp_sum(fmaf(ih0, w01, ih1 * w11));
    float p2h = warp_sum(fmaf(ih0, w02, ih1 * w12));
    float cch = warp_sum(fmaf(ih0, b0,  ih1 * b1));

    const float L2E  = 1.4426950408889634f;
    const float HL2E = 0.7213475204444817f;
    float M1l = ccl + 1.5f * (fmaxf(p0l, 0.f) + fmaxf(p1l, 0.f) + fmaxf(p2l, 0.f));
    float M1h = cch + 1.5f * (fmaxf(p0h, 0.f) + fmaxf(p1h, 0.f) + fmaxf(p2h, 0.f));
    float nM1sl = -M1l * L2E,               nM1sh = -M1h * L2E;
    float nM2sl = -(M1l + 16.0f) * HL2E,    nM2sh = -(M1h + 16.0f) * HL2E;

    float Sl = 0.f, Tl = 0.f, S2l = 0.f, gxl = 0.f, gyl = 0.f, gzl = 0.f;
    float Sh = 0.f, Th = 0.f, S2h = 0.f, gxh = 0.f, gyh = 0.f, gzh = 0.f;

    uint32_t idx = (uint32_t)rlo * 1000u + (uint32_t)lane;

    for (int n = lane; n < NC; n += 32, idx += 32) {
        float4 g = sm.grid[n];
        float xl = fmaf(p0l, g.x, fmaf(p1l, g.y, fmaf(p2l, g.z, ccl)));
        float xh = fmaf(p0h, g.x, fmaf(p1h, g.y, fmaf(p2h, g.z, cch)));

        float e1l = ex2a(fmaf(xl, L2E, nM1sl));
        float e1h = ex2a(fmaf(xh, L2E, nM1sh));
        Sl += e1l; Tl = fmaf(e1l, xl, Tl);
        Sh += e1h; Th = fmaf(e1h, xh, Th);

#if RNG_PARTITIONABLE
        U2 A = tf2x32(kc0, kc1, 0u, idx);
        U2 B = tf2x32(kc0, kc1, 0u, idx + H_COORD);
        float ltl = gumbel_lg2t(A.x ^ A.y);
        float lth = gumbel_lg2t(B.x ^ B.y);
#else
        U2 A = tf2x32(kc0, kc1, idx, idx + H_COORD);
        float ltl = gumbel_lg2t(A.x);
        float lth = gumbel_lg2t(A.y);
#endif
        // e2 = exp((x+g)/2 - M2), g = -ln2*lt  =>  exp2(x*L2E/2 - lt/2 - M2s)
        float e2l = ex2a(fmaf(xl, HL2E, fmaf(ltl, -0.5f, nM2sl)));
        float e2h = ex2a(fmaf(xh, HL2E, fmaf(lth, -0.5f, nM2sh)));
        S2l += e2l; gxl = fmaf(e2l, g.x, gxl); gyl = fmaf(e2l, g.y, gyl); gzl = fmaf(e2l, g.z, gzl);
        S2h += e2h; gxh = fmaf(e2h, g.x, gxh); gyh = fmaf(e2h, g.y, gyh); gzh = fmaf(e2h, g.z, gzh);
    }

    Sl = warp_sum(Sl); Tl = warp_sum(Tl);
    Sh = warp_sum(Sh); Th = warp_sum(Th);
    S2l = warp_sum(S2l); gxl = warp_sum(gxl); gyl = warp_sum(gyl); gzl = warp_sum(gzl);
    S2h = warp_sum(S2h); gxh = warp_sum(gxh); gyh = warp_sum(gyh); gzh = warp_sum(gzh);

    float lzl = fmaf(0.6931471805599453f, lg2a(Sl), M1l);
    float lzh = fmaf(0.6931471805599453f, lg2a(Sh), M1h);
    float kll = Tl / Sl - lzl + 6.907755278982137f;   // + log(1000)
    float klh = Th / Sh - lzh + 6.907755278982137f;

    float invl = 1.0f / S2l, invh = 1.0f / S2h;
    gxl *= invl; gyl *= invl; gzl *= invl;
    gxh *= invh; gyh *= invh; gzh *= invh;

    out[QCOFF + (size_t)rlo * 64 + lane]      = fmaf(w00, gxl, fmaf(w01, gyl, fmaf(w02, gzl, b0)));
    out[QCOFF + (size_t)rlo * 64 + 32 + lane] = fmaf(w10, gxl, fmaf(w11, gyl, fmaf(w12, gzl, b1)));
    out[QCOFF + (size_t)rhi * 64 + lane]      = fmaf(w00, gxh, fmaf(w01, gyh, fmaf(w02, gzh, b0)));
    out[QCOFF + (size_t)rhi * 64 + 32 + lane] = fmaf(w10, gxh, fmaf(w11, gyh, fmaf(w12, gzh, b1)));

    if (lane == 0) sm.kl[w] = (double)kll + (double)klh;
    __syncthreads();
    if (tid == 0) {
        double s = 0;
        #pragma unroll
        for (int i = 0; i < 8; i++) s += sm.kl[i];
        g_parts[bid] = s;
    }
}

// =======================================================================
// Per-codebook path (tiny: ~3% of cipher work) — unchanged logic.
// =======================================================================
__device__ __forceinline__ void do_code(
    CodeSm& sm, int pairBase,
    const float* __restrict__ inputs, const float* __restrict__ emb,
    const float* __restrict__ lin_ws, float* __restrict__ out,
    uint32_t kp0, uint32_t kp1, int bid)
{
    const int tid = threadIdx.x;
    for (int i = tid; i < 4096; i += 256) {
        int ke = i >> 6, d = i & 63;
        sm.lwt[d * 64 + ke] = lin_ws[i];
    }
    for (int i = tid; i < 512; i += 256)
        sm.emb_s[(i >> 4) * 17 + (i & 15)] = emb[i];
    __syncthreads();

    const int w = tid >> 5, lane = tid & 31;
    const int rlo = pairBase + w;
    const int rhi = rlo + HROWS;

    sm.in_s[w][0][lane]      = inputs[(size_t)rlo * 64 + lane];
    sm.in_s[w][0][lane + 32] = inputs[(size_t)rlo * 64 + lane + 32];
    sm.in_s[w][1][lane]      = inputs[(size_t)rhi * 64 + lane];
    sm.in_s[w][1][lane + 32] = inputs[(size_t)rhi * 64 + lane + 32];
    __syncwarp();

    float hl0 = 0.f, hl1 = 0.f, hh0 = 0.f, hh1 = 0.f;
    const float2* lwt2 = reinterpret_cast<const float2*>(sm.lwt);
    #pragma unroll 8
    for (int d = 0; d < 64; d++) {
        float2 wv = lwt2[d * 32 + lane];
        float xl = sm.in_s[w][0][d], xh = sm.in_s[w][1][d];
        hl0 = fmaf(xl, wv.x, hl0); hl1 = fmaf(xl, wv.y, hl1);
        hh0 = fmaf(xh, wv.x, hh0); hh1 = fmaf(xh, wv.y, hh1);
    }
    sm.h_s[w][0][2 * lane] = hl0; sm.h_s[w][0][2 * lane + 1] = hl1;
    sm.h_s[w][1][2 * lane] = hh0; sm.h_s[w][1][2 * lane + 1] = hh1;
    __syncwarp();

    const int kk = lane >> 3;
    float xpl = 0.f, xph = 0.f;
    #pragma unroll
    for (int e = 0; e < 16; e++) {
        float ev = sm.emb_s[lane * 17 + e];
        xpl = fmaf(sm.h_s[w][0][kk * 16 + e], ev, xpl);
        xph = fmaf(sm.h_s[w][1][kk * 16 + e], ev, xph);
    }

    float ml = grp8_max(xpl), mh = grp8_max(xph);
    float el = ex2a((xpl - ml) * 1.4426950408889634f);
    float eh = ex2a((xph - mh) * 1.4426950408889634f);
    float sl = grp8_sum(el), sh2 = grp8_sum(eh);
    float lzl = fmaf(0.6931471805599453f, lg2a(sl), ml);
    float lzh = fmaf(0.6931471805599453f, lg2a(sh2), mh);
    float lpl = xpl - lzl, lph = xph - lzh;
    float kl_l = grp8_sum(el * (lpl + 2.0794415416798357f)) / sl;
    float kl_h = grp8_sum(eh * (lph + 2.0794415416798357f)) / sh2;

    uint32_t idx = (uint32_t)rlo * 32u + (uint32_t)lane;
    float gl, gh;
#if RNG_PARTITIONABLE
    U2 A = tf2x32(kp0, kp1, 0u, idx);
    U2 B = tf2x32(kp0, kp1, 0u, idx + H_CODE);
    gl = bits_to_gumbel(A.x ^ A.y);
    gh = bits_to_gumbel(B.x ^ B.y);
#else
    U2 A = tf2x32(kp0, kp1, idx, idx + H_CODE);
    gl = bits_to_gumbel(A.x);
    gh = bits_to_gumbel(A.y);
#endif

    float zl = (lpl + gl) * 0.5f, zh = (lph + gh) * 0.5f;
    float m2l = grp8_max(zl), m2h = grp8_max(zh);
    float e2l = ex2a((zl - m2l) * 1.4426950408889634f);
    float e2h = ex2a((zh - m2h) * 1.4426950408889634f);
    float s2l = grp8_sum(e2l), s2h = grp8_sum(e2h);
    sm.ip_s[w][0][lane] = e2l / s2l;
    sm.ip_s[w][1][lane] = e2h / s2h;
    __syncwarp();

    const int k2 = lane >> 3;
    const int e0 = (2 * lane) & 15;
    float ql0 = 0.f, ql1 = 0.f, qh0 = 0.f, qh1 = 0.f;
    #pragma unroll
    for (int nn = 0; nn < 8; nn++) {
        float ipl = sm.ip_s[w][0][k2 * 8 + nn];
        float iph = sm.ip_s[w][1][k2 * 8 + nn];
        float ev0 = sm.emb_s[(k2 * 8 + nn) * 17 + e0];
        float ev1 = sm.emb_s[(k2 * 8 + nn) * 17 + e0 + 1];
        ql0 = fmaf(ipl, ev0, ql0); ql1 = fmaf(ipl, ev1, ql1);
        qh0 = fmaf(iph, ev0, qh0); qh1 = fmaf(iph, ev1, qh1);
    }
    float2* o2 = reinterpret_cast<float2*>(out);
    o2[(size_t)rlo * 32 + lane] = make_float2(ql0, ql1);
    o2[(size_t)rhi * 32 + lane] = make_float2(qh0, qh1);

    float klrow = ((lane & 7) == 0) ? (kl_l + kl_h) : 0.0f;
    klrow = warp_sum(klrow);
    if (lane == 0) sm.kl[w] = (double)klrow;
    __syncthreads();
    if (tid == 0) {
        double s = 0;
        #pragma unroll
        for (int i = 0; i < 8; i++) s += sm.kl[i];
        g_parts[bid] = s;
    }
}

// Fused kernel: even blocks -> coord, odd blocks -> code (pipe mixing:
// alu-bound coord warps co-reside with fma-bound code warps).
__global__ void __launch_bounds__(256, 3)
k_fused(const float* __restrict__ inputs, const float* __restrict__ linear_w,
        const float* __restrict__ linear_b, const float* __restrict__ emb,
        const float* __restrict__ lin_ws, float* __restrict__ out,
        uint32_t kc0, uint32_t kc1, uint32_t kp0, uint32_t kp1)
{
    __shared__ SmU sm;
    const int bid = blockIdx.x;
    const int pairBase = (bid >> 1) * 8;
    if ((bid & 1) == 0)
        do_coord(sm.c, pairBase, inputs, linear_w, linear_b, out, kc0, kc1, bid);
    else
        do_code(sm.q, pairBase, inputs, emb, lin_ws, out, kp0, kp1, bid);
}

// Deterministic final reduction of the KL partials -> loss scalar
__global__ void k_final(float* __restrict__ out, int loss_idx) {
    __shared__ double sh[256];
    double s = 0;
    for (int i = threadIdx.x; i < 8192; i += 256) s += g_parts[i];
    sh[threadIdx.x] = s;
    __syncthreads();
    #pragma unroll
    for (int o = 128; o; o >>= 1) {
        if (threadIdx.x < o) sh[threadIdx.x] += sh[threadIdx.x + o];
        __syncthreads();
    }
    if (threadIdx.x == 0) out[loss_idx] = (float)(sh[0] / 5.0);
}

extern "C" void kernel_launch(void* const* d_in, const int* in_sizes, int n_in,
                              void* d_out, int out_size) {
    const float* inputs   = (const float*)d_in[0];
    const float* linear_w = (const float*)d_in[1];
    const float* linear_b = (const float*)d_in[2];
    const float* emb      = (const float*)d_in[3];
    const float* lin_ws   = (const float*)d_in[4];
    float* out = (float*)d_out;

    // kc, kp = jax.random.split(jax.random.key(42))
#if RNG_PARTITIONABLE
    U2 a = tf2x32(0u, 42u, 0u, 0u);
    U2 b = tf2x32(0u, 42u, 0u, 1u);
    uint32_t kc0 = a.x, kc1 = a.y;
    uint32_t kp0 = b.x, kp1 = b.y;
#else
    U2 a = tf2x32(0u, 42u, 0u, 2u);
    U2 b = tf2x32(0u, 42u, 1u, 3u);
    uint32_t kc0 = a.x, kc1 = b.x;
    uint32_t kp0 = a.y, kp1 = b.y;
#endif

    k_fused<<<8192, 256>>>(inputs, linear_w, linear_b, emb, lin_ws, out,
                           kc0, kc1, kp0, kp1);
    k_final<<<1, 256>>>(out, out_size - 1);
}

// round 5
// speedup vs baseline: 1.5153x; 1.2778x over previous
#include <cuda_runtime.h>
#include <cstdint>

// jax threefry mode: 1 = threefry_partitionable (jax >= 0.5.0 default), 0 = legacy
#ifndef RNG_PARTITIONABLE
#define RNG_PARTITIONABLE 1
#endif

#define HROWS  32768
#define NC     1000
#define H_COORD 32768000u   // half of 32*2048*1000
#define H_CODE  1048576u    // half of 32*2048*32
#define QCOFF  4194304      // 65536*64

__device__ double g_parts[8192];
__device__ unsigned int g_done;   // zero-initialized; reset by last block each run

// ---------------- threefry2x32 (matches jax) ----------------
__host__ __device__ __forceinline__ uint32_t rotl32(uint32_t x, int r) {
#ifdef __CUDA_ARCH__
    return __funnelshift_l(x, x, r);
#else
    return (x << r) | (x >> (32 - r));
#endif
}

struct U2 { uint32_t x, y; };

// Precomputed key-injection schedule: after round-group j, x0 += A[j], x1 += B[j].
struct TFK {
    uint32_t a0, b0, a1, b1, a2, b2, a3, b3, a4, b4, a5, b5;
};

__host__ inline TFK make_tfk(uint32_t k0, uint32_t k1) {
    uint32_t k2 = k0 ^ k1 ^ 0x1BD11BDAu;
    TFK K;
    K.a0 = k0; K.b0 = k1;
    K.a1 = k1; K.b1 = k2 + 1u;
    K.a2 = k2; K.b2 = k0 + 2u;
    K.a3 = k0; K.b3 = k1 + 3u;
    K.a4 = k1; K.b4 = k2 + 4u;
    K.a5 = k2; K.b5 = k0 + 5u;
    return K;
}

// host-side plain cipher (for key derivation)
__host__ inline U2 tf_host(uint32_t k0, uint32_t k1, uint32_t x0, uint32_t x1) {
    uint32_t k2 = k0 ^ k1 ^ 0x1BD11BDAu;
    x0 += k0; x1 += k1;
#define TFR(r) { x0 += x1; x1 = rotl32(x1, r); x1 ^= x0; }
    TFR(13) TFR(15) TFR(26) TFR(6)
    x0 += k1; x1 += k2 + 1u;
    TFR(17) TFR(29) TFR(16) TFR(24)
    x0 += k2; x1 += k0 + 2u;
    TFR(13) TFR(15) TFR(26) TFR(6)
    x0 += k0; x1 += k1 + 3u;
    TFR(17) TFR(29) TFR(16) TFR(24)
    x0 += k1; x1 += k2 + 4u;
    TFR(13) TFR(15) TFR(26) TFR(6)
    x0 += k2; x1 += k0 + 5u;
#undef TFR
    U2 r; r.x = x0; r.y = x1; return r;
}

// Integer add forced onto the FMA pipe: IMAD r = a*one + b, with `one` an
// opaque runtime value (kernel arg == 1) so ptxas cannot fold it to IADD3.
__device__ __forceinline__ uint32_t addi(uint32_t a, uint32_t b, uint32_t one) {
    uint32_t r;
    asm("mad.lo.u32 %0, %1, %2, %3;" : "=r"(r) : "r"(a), "r"(one), "r"(b));
    return r;
}

// Device cipher: round adds + x1 injections on fma pipe (IMAD), x0 injections
// and SHF/LOP3 on alu pipe — balances the two 2-op/cyc/SM pipes.
__device__ __forceinline__ U2 tf_dev(uint32_t x0, uint32_t x1, const TFK K, uint32_t one) {
#define TFRD(r) { x0 = addi(x0, x1, one); x1 = rotl32(x1, r) ^ x0; }
    x0 += K.a0; x1 = addi(x1, K.b0, one);
    TFRD(13) TFRD(15) TFRD(26) TFRD(6)
    x0 += K.a1; x1 = addi(x1, K.b1, one);
    TFRD(17) TFRD(29) TFRD(16) TFRD(24)
    x0 += K.a2; x1 = addi(x1, K.b2, one);
    TFRD(13) TFRD(15) TFRD(26) TFRD(6)
    x0 += K.a3; x1 = addi(x1, K.b3, one);
    TFRD(17) TFRD(29) TFRD(16) TFRD(24)
    x0 += K.a4; x1 = addi(x1, K.b4, one);
    TFRD(13) TFRD(15) TFRD(26) TFRD(6)
    x0 += K.a5; x1 = addi(x1, K.b5, one);
#undef TFRD
    U2 r; r.x = x0; r.y = x1; return r;
}

__device__ __forceinline__ float ex2a(float x) {
    float r; asm("ex2.approx.ftz.f32 %0, %1;" : "=f"(r) : "f"(x)); return r;
}
__device__ __forceinline__ float lg2a(float x) {
    float r; asm("lg2.approx.ftz.f32 %0, %1;" : "=f"(r) : "f"(x)); return r;
}

// Returns lg2(t), t = 1e-20 - ln(u + 1e-20); gumbel g = -ln2 * lg2(t).
// log1p polynomial near u==1 keeps relative accuracy where MUFU's absolute
// error would blow up. __umulhi does bits>>9 on the fma pipe.
__device__ __forceinline__ float gumbel_lg2t(uint32_t bits) {
    uint32_t hi = __umulhi(bits, 0x00800000u);           // bits >> 9
    float u = __uint_as_float(hi | 0x3f800000u) - 1.0f;
    float d = 1.0f - u;                        // exact (Sterbenz) for u >= 0.5
    float poly = -d * fmaf(d, fmaf(d, fmaf(d, 0.25f, 0.33333334f), 0.5f), 1.0f);
    float lf = 0.6931471805599453f * lg2a(u + 1e-20f);
    float lnu = (d <= 0.0625f) ? poly : lf;    // ln(u + eps) <= 0
    return lg2a(1e-20f - lnu);
}

__device__ __forceinline__ float bits_to_gumbel(uint32_t bits) {
    return -0.6931471805599453f * gumbel_lg2t(bits);
}

__device__ __forceinline__ float warp_sum(float v) {
    #pragma unroll
    for (int o = 16; o; o >>= 1) v += __shfl_xor_sync(0xffffffffu, v, o);
    return v;
}
__device__ __forceinline__ float grp8_max(float v) {
    v = fmaxf(v, __shfl_xor_sync(0xffffffffu, v, 4));
    v = fmaxf(v, __shfl_xor_sync(0xffffffffu, v, 2));
    v = fmaxf(v, __shfl_xor_sync(0xffffffffu, v, 1));
    return v;
}
__device__ __forceinline__ float grp8_sum(float v) {
    v += __shfl_xor_sync(0xffffffffu, v, 4);
    v += __shfl_xor_sync(0xffffffffu, v, 2);
    v += __shfl_xor_sync(0xffffffffu, v, 1);
    return v;
}

// ---------------- shared-memory layouts ----------------
struct CoordSm {
    float4 grid[NC];
    float  Ws[192];
    float  bs[64];
    double kl[8];
};
struct CodeSm {
    float  lwt[4096];
    float  emb_s[32 * 17];
    float  in_s[8][2][64];
    float  h_s[8][2][64];
    float  ip_s[8][2][32];
    double kl[8];
};
union SmU { CoordSm c; CodeSm q; };

// =======================================================================
// Coordinate path: branch-free streaming loop; exact max known up front.
// =======================================================================
__device__ __forceinline__ void do_coord(
    CoordSm& sm, int pairBase,
    const float* __restrict__ inputs, const float* __restrict__ linear_w,
    const float* __restrict__ linear_b, float* __restrict__ out,
    const TFK Kc, uint32_t one, int bid)
{
    const int tid = threadIdx.x;
    for (int i = tid; i < 192; i += 256) sm.Ws[i] = linear_w[i];
    for (int i = tid; i < 64;  i += 256) sm.bs[i] = linear_b[i];
    for (int n = tid; n < NC; n += 256) {
        int i10 = n / 100, j10 = (n / 10) % 10, k10 = n % 10;
        // meshgrid 'xy': g[n] = (x[j], x[i], x[k])
        sm.grid[n] = make_float4((float)(j10 * (1.5 / 9.0)),
                                 (float)(i10 * (1.5 / 9.0)),
                                 (float)(k10 * (1.5 / 9.0)), 0.0f);
    }
    __syncthreads();

    const int w = tid >> 5, lane = tid & 31;
    const int rlo = pairBase + w;
    const int rhi = rlo + HROWS;

    float il0 = inputs[(size_t)rlo * 64 + lane];
    float il1 = inputs[(size_t)rlo * 64 + 32 + lane];
    float ih0 = inputs[(size_t)rhi * 64 + lane];
    float ih1 = inputs[(size_t)rhi * 64 + 32 + lane];
    float w00 = sm.Ws[lane * 3 + 0], w01 = sm.Ws[lane * 3 + 1], w02 = sm.Ws[lane * 3 + 2];
    float w10 = sm.Ws[(lane + 32) * 3 + 0], w11 = sm.Ws[(lane + 32) * 3 + 1], w12 = sm.Ws[(lane + 32) * 3 + 2];
    float b0 = sm.bs[lane], b1 = sm.bs[lane + 32];

    float p0l = warp_sum(fmaf(il0, w00, il1 * w10));
    float p1l = warp_sum(fmaf(il0, w01, il1 * w11));
    float p2l = warp_sum(fmaf(il0, w02, il1 * w12));
    float ccl = warp_sum(fmaf(il0, b0,  il1 * b1));
    float p0h = warp_sum(fmaf(ih0, w00, ih1 * w10));
    float p1h = warp_sum(fmaf(ih0, w01, ih1 * w11));
    float p2h = warp_sum(fmaf(ih0, w02, ih1 * w12));
    float cch = warp_sum(fmaf(ih0, b0,  ih1 * b1));

    const float L2E  = 1.4426950408889634f;
    const float HL2E = 0.7213475204444817f;
    // exact max of x = p.g + c over the grid (corners are grid points);
    // gumbel bounded in [-3.84, 15.95] => fixed shift (M1+16)/2 is safe.
    float M1l = ccl + 1.5f * (fmaxf(p0l, 0.f) + fmaxf(p1l, 0.f) + fmaxf(p2l, 0.f));
    float M1h = cch + 1.5f * (fmaxf(p0h, 0.f) + fmaxf(p1h, 0.f) + fmaxf(p2h, 0.f));
    float nM1sl = -M1l * L2E,            nM1sh = -M1h * L2E;
    float nM2sl = -(M1l + 16.0f) * HL2E, nM2sh = -(M1h + 16.0f) * HL2E;

    float Sl = 0.f, Tl = 0.f, S2l = 0.f, gxl = 0.f, gyl = 0.f, gzl = 0.f;
    float Sh = 0.f, Th = 0.f, S2h = 0.f, gxh = 0.f, gyh = 0.f, gzh = 0.f;

    uint32_t idx = (uint32_t)rlo * 1000u + (uint32_t)lane;

    for (int n = lane; n < NC; n += 32, idx += 32) {
        float4 g = sm.grid[n];
        float xl = fmaf(p0l, g.x, fmaf(p1l, g.y, fmaf(p2l, g.z, ccl)));
        float xh = fmaf(p0h, g.x, fmaf(p1h, g.y, fmaf(p2h, g.z, cch)));

        float e1l = ex2a(fmaf(xl, L2E, nM1sl));
        float e1h = ex2a(fmaf(xh, L2E, nM1sh));
        Sl += e1l; Tl = fmaf(e1l, xl, Tl);
        Sh += e1h; Th = fmaf(e1h, xh, Th);

#if RNG_PARTITIONABLE
        U2 A = tf_dev(0u, idx, Kc, one);
        U2 B = tf_dev(0u, idx + H_COORD, Kc, one);
        float ltl = gumbel_lg2t(A.x ^ A.y);
        float lth = gumbel_lg2t(B.x ^ B.y);
#else
        U2 A = tf_dev(idx, idx + H_COORD, Kc, one);
        float ltl = gumbel_lg2t(A.x);
        float lth = gumbel_lg2t(A.y);
#endif
        float e2l = ex2a(fmaf(xl, HL2E, fmaf(ltl, -0.5f, nM2sl)));
        float e2h = ex2a(fmaf(xh, HL2E, fmaf(lth, -0.5f, nM2sh)));
        S2l += e2l; gxl = fmaf(e2l, g.x, gxl); gyl = fmaf(e2l, g.y, gyl); gzl = fmaf(e2l, g.z, gzl);
        S2h += e2h; gxh = fmaf(e2h, g.x, gxh); gyh = fmaf(e2h, g.y, gyh); gzh = fmaf(e2h, g.z, gzh);
    }

    Sl = warp_sum(Sl); Tl = warp_sum(Tl);
    Sh = warp_sum(Sh); Th = warp_sum(Th);
    S2l = warp_sum(S2l); gxl = warp_sum(gxl); gyl = warp_sum(gyl); gzl = warp_sum(gzl);
    S2h = warp_sum(S2h); gxh = warp_sum(gxh); gyh = warp_sum(gyh); gzh = warp_sum(gzh);

    float lzl = fmaf(0.6931471805599453f, lg2a(Sl), M1l);
    float lzh = fmaf(0.6931471805599453f, lg2a(Sh), M1h);
    float kll = Tl / Sl - lzl + 6.907755278982137f;
    float klh = Th / Sh - lzh + 6.907755278982137f;

    float invl = 1.0f / S2l, invh = 1.0f / S2h;
    gxl *= invl; gyl *= invl; gzl *= invl;
    gxh *= invh; gyh *= invh; gzh *= invh;

    out[QCOFF + (size_t)rlo * 64 + lane]      = fmaf(w00, gxl, fmaf(w01, gyl, fmaf(w02, gzl, b0)));
    out[QCOFF + (size_t)rlo * 64 + 32 + lane] = fmaf(w10, gxl, fmaf(w11, gyl, fmaf(w12, gzl, b1)));
    out[QCOFF + (size_t)rhi * 64 + lane]      = fmaf(w00, gxh, fmaf(w01, gyh, fmaf(w02, gzh, b0)));
    out[QCOFF + (size_t)rhi * 64 + 32 + lane] = fmaf(w10, gxh, fmaf(w11, gyh, fmaf(w12, gzh, b1)));

    if (lane == 0) sm.kl[w] = (double)kll + (double)klh;
    __syncthreads();
    if (tid == 0) {
        double s = 0;
        #pragma unroll
        for (int i = 0; i < 8; i++) s += sm.kl[i];
        g_parts[bid] = s;
    }
}

// =======================================================================
// Per-codebook path (tiny: ~3% of cipher work).
// =======================================================================
__device__ __forceinline__ void do_code(
    CodeSm& sm, int pairBase,
    const float* __restrict__ inputs, const float* __restrict__ emb,
    const float* __restrict__ lin_ws, float* __restrict__ out,
    const TFK Kp, uint32_t one, int bid)
{
    const int tid = threadIdx.x;
    for (int i = tid; i < 4096; i += 256) {
        int ke = i >> 6, d = i & 63;
        sm.lwt[d * 64 + ke] = lin_ws[i];
    }
    for (int i = tid; i < 512; i += 256)
        sm.emb_s[(i >> 4) * 17 + (i & 15)] = emb[i];
    __syncthreads();

    const int w = tid >> 5, lane = tid & 31;
    const int rlo = pairBase + w;
    const int rhi = rlo + HROWS;

    sm.in_s[w][0][lane]      = inputs[(size_t)rlo * 64 + lane];
    sm.in_s[w][0][lane + 32] = inputs[(size_t)rlo * 64 + lane + 32];
    sm.in_s[w][1][lane]      = inputs[(size_t)rhi * 64 + lane];
    sm.in_s[w][1][lane + 32] = inputs[(size_t)rhi * 64 + lane + 32];
    __syncwarp();

    float hl0 = 0.f, hl1 = 0.f, hh0 = 0.f, hh1 = 0.f;
    const float2* lwt2 = reinterpret_cast<const float2*>(sm.lwt);
    #pragma unroll 8
    for (int d = 0; d < 64; d++) {
        float2 wv = lwt2[d * 32 + lane];
        float xl = sm.in_s[w][0][d], xh = sm.in_s[w][1][d];
        hl0 = fmaf(xl, wv.x, hl0); hl1 = fmaf(xl, wv.y, hl1);
        hh0 = fmaf(xh, wv.x, hh0); hh1 = fmaf(xh, wv.y, hh1);
    }
    sm.h_s[w][0][2 * lane] = hl0; sm.h_s[w][0][2 * lane + 1] = hl1;
    sm.h_s[w][1][2 * lane] = hh0; sm.h_s[w][1][2 * lane + 1] = hh1;
    __syncwarp();

    const int kk = lane >> 3;
    float xpl = 0.f, xph = 0.f;
    #pragma unroll
    for (int e = 0; e < 16; e++) {
        float ev = sm.emb_s[lane * 17 + e];
        xpl = fmaf(sm.h_s[w][0][kk * 16 + e], ev, xpl);
        xph = fmaf(sm.h_s[w][1][kk * 16 + e], ev, xph);
    }

    float ml = grp8_max(xpl), mh = grp8_max(xph);
    float el = ex2a((xpl - ml) * 1.4426950408889634f);
    float eh = ex2a((xph - mh) * 1.4426950408889634f);
    float sl = grp8_sum(el), sh2 = grp8_sum(eh);
    float lzl = fmaf(0.6931471805599453f, lg2a(sl), ml);
    float lzh = fmaf(0.6931471805599453f, lg2a(sh2), mh);
    float lpl = xpl - lzl, lph = xph - lzh;
    float kl_l = grp8_sum(el * (lpl + 2.0794415416798357f)) / sl;
    float kl_h = grp8_sum(eh * (lph + 2.0794415416798357f)) / sh2;

    uint32_t idx = (uint32_t)rlo * 32u + (uint32_t)lane;
    float gl, gh;
#if RNG_PARTITIONABLE
    U2 A = tf_dev(0u, idx, Kp, one);
    U2 B = tf_dev(0u, idx + H_CODE, Kp, one);
    gl = bits_to_gumbel(A.x ^ A.y);
    gh = bits_to_gumbel(B.x ^ B.y);
#else
    U2 A = tf_dev(idx, idx + H_CODE, Kp, one);
    gl = bits_to_gumbel(A.x);
    gh = bits_to_gumbel(A.y);
#endif

    float zl = (lpl + gl) * 0.5f, zh = (lph + gh) * 0.5f;
    float m2l = grp8_max(zl), m2h = grp8_max(zh);
    float e2l = ex2a((zl - m2l) * 1.4426950408889634f);
    float e2h = ex2a((zh - m2h) * 1.4426950408889634f);
    float s2l = grp8_sum(e2l), s2h = grp8_sum(e2h);
    sm.ip_s[w][0][lane] = e2l / s2l;
    sm.ip_s[w][1][lane] = e2h / s2h;
    __syncwarp();

    const int k2 = lane >> 3;
    const int e0 = (2 * lane) & 15;
    float ql0 = 0.f, ql1 = 0.f, qh0 = 0.f, qh1 = 0.f;
    #pragma unroll
    for (int nn = 0; nn < 8; nn++) {
        float ipl = sm.ip_s[w][0][k2 * 8 + nn];
        float iph = sm.ip_s[w][1][k2 * 8 + nn];
        float ev0 = sm.emb_s[(k2 * 8 + nn) * 17 + e0];
        float ev1 = sm.emb_s[(k2 * 8 + nn) * 17 + e0 + 1];
        ql0 = fmaf(ipl, ev0, ql0); ql1 = fmaf(ipl, ev1, ql1);
        qh0 = fmaf(iph, ev0, qh0); qh1 = fmaf(iph, ev1, qh1);
    }
    float2* o2 = reinterpret_cast<float2*>(out);
    o2[(size_t)rlo * 32 + lane] = make_float2(ql0, ql1);
    o2[(size_t)rhi * 32 + lane] = make_float2(qh0, qh1);

    float klrow = ((lane & 7) == 0) ? (kl_l + kl_h) : 0.0f;
    klrow = warp_sum(klrow);
    if (lane == 0) sm.kl[w] = (double)klrow;
    __syncthreads();
    if (tid == 0) {
        double s = 0;
        #pragma unroll
        for (int i = 0; i < 8; i++) s += sm.kl[i];
        g_parts[bid] = s;
    }
}

// Fused kernel: even blocks -> coord, odd blocks -> code. Last block to
// finish reduces the KL partials into the loss (saves a trailing launch).
__global__ void __launch_bounds__(256, 3)
k_fused(const float* __restrict__ inputs, const float* __restrict__ linear_w,
        const float* __restrict__ linear_b, const float* __restrict__ emb,
        const float* __restrict__ lin_ws, float* __restrict__ out,
        TFK Kc, TFK Kp, uint32_t one, int loss_idx)
{
    __shared__ SmU sm;
    __shared__ int is_last;
    const int bid = blockIdx.x;
    const int pairBase = (bid >> 1) * 8;
    if ((bid & 1) == 0)
        do_coord(sm.c, pairBase, inputs, linear_w, linear_b, out, Kc, one, bid);
    else
        do_code(sm.q, pairBase, inputs, emb, lin_ws, out, Kp, one, bid);

    // last-block loss reduction (deterministic order within the last block)
    __threadfence();
    if (threadIdx.x == 0) {
        unsigned int prev = atomicAdd(&g_done, 1u);
        is_last = (prev == gridDim.x - 1u);
    }
    __syncthreads();
    if (is_last) {
        __shared__ double red[256];
        double s = 0;
        for (int i = threadIdx.x; i < 8192; i += 256) s += g_parts[i];
        red[threadIdx.x] = s;
        __syncthreads();
        #pragma unroll
        for (int o = 128; o; o >>= 1) {
            if (threadIdx.x < o) red[threadIdx.x] += red[threadIdx.x + o];
            __syncthreads();
        }
        if (threadIdx.x == 0) {
            out[loss_idx] = (float)(red[0] / 5.0);
            g_done = 0;   // reset for next graph replay
        }
    }
}

extern "C" void kernel_launch(void* const* d_in, const int* in_sizes, int n_in,
                              void* d_out, int out_size) {
    const float* inputs   = (const float*)d_in[0];
    const float* linear_w = (const float*)d_in[1];
    const float* linear_b = (const float*)d_in[2];
    const float* emb      = (const float*)d_in[3];
    const float* lin_ws   = (const float*)d_in[4];
    float* out = (float*)d_out;

    // kc, kp = jax.random.split(jax.random.key(42))
#if RNG_PARTITIONABLE
    U2 a = tf_host(0u, 42u, 0u, 0u);
    U2 b = tf_host(0u, 42u, 0u, 1u);
    uint32_t kc0 = a.x, kc1 = a.y;
    uint32_t kp0 = b.x, kp1 = b.y;
#else
    U2 a = tf_host(0u, 42u, 0u, 2u);
    U2 b = tf_host(0u, 42u, 1u, 3u);
    uint32_t kc0 = a.x, kc1 = b.x;
    uint32_t kp0 = a.y, kp1 = b.y;
#endif
    TFK Kc = make_tfk(kc0, kc1);
    TFK Kp = make_tfk(kp0, kp1);

    k_fused<<<8192, 256>>>(inputs, linear_w, linear_b, emb, lin_ws, out,
                           Kc, Kp, 1u, out_size - 1);
}